// round 10
// baseline (speedup 1.0000x reference)
#include <cuda_runtime.h>
#include <cuda_fp16.h>
#include <cstdint>

#define P_    8
#define T_    2048
#define N_    8192
#define M_    20000
#define DLAT  1024
#define DFEAT 512
#define DIN   1536
#define MSPLIT 10
#define MCHUNK 2000
#define NSCH  8
#define SCHSZ 1024

// ---- GEMM config (round-5 proven shape) ----
#define BM 128
#define BN 128
#define BK 64
#define NSTG 3
#define STG_BYTES 32768                // A 16K + B 16K
#define GEMM_SMEM (NSTG * STG_BYTES)   // 96KB

// ---------------- scratch ----------------
__device__ float g_part_d[N_ * MSPLIT];
__device__ int   g_part_i[N_ * MSPLIT];
__device__ int   g_nearest[N_];
__device__ float g_mp_d[2 * P_ * NSCH * T_];
__device__ int   g_mp_i[2 * P_ * NSCH * T_];
__device__ int   g_match2[2 * P_ * T_];          // [which][p][t] -> obj-point idx
__device__ __half g_A[2L * P_ * T_ * DLAT];      // [z][m][k<1024] fp16
__device__ __half g_PF[(size_t)N_ * DFEAT];      // fp16 feats per obj point
__device__ __half g_B1[2L * DLAT * DLAT];        // W[:1024]^T fp16 [z][n][k]
__device__ __half g_B2[2L * DLAT * DFEAT];       // W[1024:]^T fp16 [z][n][k]
__device__ __half g_pf2u[2L * N_ * DLAT];        // fp16 pf @ W2 per obj point (32MB)

// ---------------- helpers ----------------
__device__ __forceinline__ uint32_t smem_u32(const void* p) {
    uint32_t a;
    asm("{ .reg .u64 t; cvta.to.shared.u64 t, %1; cvt.u32.u64 %0, t; }" : "=r"(a) : "l"(p));
    return a;
}
__device__ __forceinline__ void cp16(uint32_t dst, const void* src) {
    asm volatile("cp.async.cg.shared.global [%0], [%1], 16;" :: "r"(dst), "l"(src) : "memory");
}
#define CP_COMMIT() asm volatile("cp.async.commit_group;" ::: "memory")
#define CP_WAIT1()  asm volatile("cp.async.wait_group 1;" ::: "memory")

__device__ __forceinline__ void ldmx4(uint32_t addr, uint32_t& r0, uint32_t& r1,
                                      uint32_t& r2, uint32_t& r3) {
    asm volatile("ldmatrix.sync.aligned.m8n8.x4.shared.b16 {%0,%1,%2,%3}, [%4];"
                 : "=r"(r0), "=r"(r1), "=r"(r2), "=r"(r3) : "r"(addr));
}
__device__ __forceinline__ void mma16816(float& c0, float& c1, float& c2, float& c3,
                                         uint32_t a0, uint32_t a1, uint32_t a2, uint32_t a3,
                                         uint32_t b0, uint32_t b1) {
    asm volatile("mma.sync.aligned.m16n8k16.row.col.f32.f16.f16.f32 "
                 "{%0,%1,%2,%3}, {%4,%5,%6,%7}, {%8,%9}, {%0,%1,%2,%3};"
                 : "+f"(c0), "+f"(c1), "+f"(c2), "+f"(c3)
                 : "r"(a0), "r"(a1), "r"(a2), "r"(a3), "r"(b0), "r"(b1));
}
__device__ __forceinline__ uint32_t swz(int row, int kg) {
    return (uint32_t)(row * 128 + ((kg ^ (row & 7)) << 4));
}
__device__ __forceinline__ uint2 pack4h(float4 v) {
    __half hx = __float2half_rn(v.x), hy = __float2half_rn(v.y);
    __half hz = __float2half_rn(v.z), hw = __float2half_rn(v.w);
    uint2 r;
    r.x = ((uint32_t)*(uint16_t*)&hy << 16) | (uint32_t)*(uint16_t*)&hx;
    r.y = ((uint32_t)*(uint16_t*)&hw << 16) | (uint32_t)*(uint16_t*)&hz;
    return r;
}

// ---------------- kernel 1: obj_pts[0] vs precomputed_points (4 q/thread) ----------------
__global__ void nn1_partial(const float* __restrict__ os, const float* __restrict__ pts) {
    __shared__ float4 sP[MCHUNK];
    const int ms = blockIdx.y;
    const int m0 = ms * MCHUNK;
    for (int i = threadIdx.x; i < MCHUNK; i += 128) {
        float x = pts[(size_t)(m0 + i) * 3 + 0];
        float y = pts[(size_t)(m0 + i) * 3 + 1];
        float z = pts[(size_t)(m0 + i) * 3 + 2];
        sP[i] = make_float4(x, y, z, x * x + y * y + z * z);
    }
    __syncthreads();
    float qx[4], qy[4], qz[4], best[4];
    int bi[4];
    #pragma unroll
    for (int u = 0; u < 4; u++) {
        const int q = blockIdx.x * 512 + u * 128 + threadIdx.x;
        qx[u] = -2.0f * os[(size_t)q * 6 + 0];
        qy[u] = -2.0f * os[(size_t)q * 6 + 1];
        qz[u] = -2.0f * os[(size_t)q * 6 + 2];
        best[u] = 3.4e38f;
        bi[u] = 0;
    }
    #pragma unroll 4
    for (int i = 0; i < MCHUNK; i++) {
        float4 c = sP[i];
        #pragma unroll
        for (int u = 0; u < 4; u++) {
            float d = fmaf(qx[u], c.x, fmaf(qy[u], c.y, fmaf(qz[u], c.z, c.w)));
            if (d < best[u]) { best[u] = d; bi[u] = i; }
        }
    }
    #pragma unroll
    for (int u = 0; u < 4; u++) {
        const int q = blockIdx.x * 512 + u * 128 + threadIdx.x;
        g_part_d[q * MSPLIT + ms] = best[u];
        g_part_i[q * MSPLIT + ms] = m0 + bi[u];
    }
}

__global__ void nn1_reduce() {
    const int q = blockIdx.x * blockDim.x + threadIdx.x;
    float best = g_part_d[q * MSPLIT];
    int bi = g_part_i[q * MSPLIT];
    #pragma unroll
    for (int s = 1; s < MSPLIT; s++) {
        float d = g_part_d[q * MSPLIT + s];
        if (d < best) { best = d; bi = g_part_i[q * MSPLIT + s]; }
    }
    g_nearest[q] = bi;
}

// ---------------- kernel 2: match partial + reduce ----------------
__global__ void match_partial(const float* __restrict__ os,
                              const float* __restrict__ local_pc,
                              const float* __restrict__ global_pc) {
    __shared__ float4 sP[SCHSZ];
    const int p = blockIdx.y;
    const int which = blockIdx.z >> 3;
    const int ch = blockIdx.z & 7;
    const int nt = ch * SCHSZ;
    const float* qsrc = (which == 0) ? local_pc : global_pc;
    const int tb = blockIdx.x * 1024 + threadIdx.x;

    for (int i = threadIdx.x; i < SCHSZ; i += 256) {
        size_t bsrc = ((size_t)p * N_ + nt + i) * 6;
        float x = os[bsrc + 0], y = os[bsrc + 1], z = os[bsrc + 2];
        sP[i] = make_float4(x, y, z, x * x + y * y + z * z);
    }

    float qx[4], qy[4], qz[4], best[4];
    int bi[4];
    #pragma unroll
    for (int u = 0; u < 4; u++) {
        const size_t qb = ((size_t)p * T_ + tb + u * 256) * 3;
        qx[u] = -2.0f * qsrc[qb + 0];
        qy[u] = -2.0f * qsrc[qb + 1];
        qz[u] = -2.0f * qsrc[qb + 2];
        best[u] = 3.4e38f;
        bi[u] = 0;
    }
    __syncthreads();
    #pragma unroll 4
    for (int i = 0; i < SCHSZ; i++) {
        float4 c = sP[i];
        #pragma unroll
        for (int u = 0; u < 4; u++) {
            float d = fmaf(qx[u], c.x, fmaf(qy[u], c.y, fmaf(qz[u], c.z, c.w)));
            if (d < best[u]) { best[u] = d; bi[u] = nt + i; }
        }
    }
    #pragma unroll
    for (int u = 0; u < 4; u++) {
        size_t o = (((size_t)which * P_ + p) * NSCH + ch) * T_ + tb + u * 256;
        g_mp_d[o] = best[u];
        g_mp_i[o] = bi[u];
    }
}

__global__ void match_reduce() {
    const int g = blockIdx.x * 256 + threadIdx.x;
    const int wp = g / T_;
    const int t = g % T_;
    size_t base = ((size_t)wp * NSCH) * T_ + t;
    float best = g_mp_d[base];
    int bi = g_mp_i[base];
    #pragma unroll
    for (int c = 1; c < NSCH; c++) {
        float d = g_mp_d[base + (size_t)c * T_];
        if (d < best) { best = d; bi = g_mp_i[base + (size_t)c * T_]; }
    }
    g_match2[g] = bi;
}

// ---------------- conversions ----------------
__global__ void convA(const float* __restrict__ geo_raw, const float* __restrict__ obj_raw) {
    const int z = blockIdx.y;
    const int m = blockIdx.x;
    const float* src = (z ? obj_raw : geo_raw) + (size_t)m * DLAT + threadIdx.x * 4;
    float4 v = *(const float4*)src;
    size_t base = ((size_t)z * (P_ * T_) + m) * DLAT + threadIdx.x * 4;
    *(uint2*)(g_A + base) = pack4h(v);
}

__global__ void gatherPF(const float* __restrict__ pf) {
    const int q = blockIdx.x;
    const int fi = g_nearest[q];
    float4 v = *(const float4*)(pf + (size_t)fi * DFEAT + threadIdx.x * 4);
    *(uint2*)(g_PF + (size_t)q * DFEAT + threadIdx.x * 4) = pack4h(v);
}

__global__ void convW(const float* __restrict__ Wg, const float* __restrict__ Wo) {
    __shared__ float tile[32][33];
    const int g = blockIdx.z;
    const float* W = g ? Wo : Wg;
    const int kb = blockIdx.x * 32, nb = blockIdx.y * 32;
    for (int i = threadIdx.y; i < 32; i += 8)
        tile[i][threadIdx.x] = W[(size_t)(kb + i) * DLAT + nb + threadIdx.x];
    __syncthreads();
    const int k = kb + threadIdx.x;
    for (int i = threadIdx.y; i < 32; i += 8) {
        __half h = __float2half_rn(tile[threadIdx.x][i]);
        const int n = nb + i;
        if (k < DLAT)
            g_B1[(size_t)g * DLAT * DLAT + (size_t)n * DLAT + k] = h;
        else
            g_B2[(size_t)g * DLAT * DFEAT + (size_t)n * DFEAT + (k - DLAT)] = h;
    }
}

// ---------------- GEMM: mode 0 = fp32 C + bias ; mode 1 = fp16 C raw ----------------
extern __shared__ char dynsmem[];

__device__ __forceinline__ void load_chunk(uint32_t sbase, int stage, int kglob, int kdim,
                                           const __half* A, const __half* B,
                                           int m0, int n0, int tid) {
    const uint32_t st = sbase + stage * STG_BYTES;
    #pragma unroll
    for (int p = 0; p < 4; p++) {
        int lin = p * 256 + tid;
        int row = lin >> 3, kg = lin & 7;
        cp16(st + swz(row, kg), A + (size_t)(m0 + row) * kdim + kglob + kg * 8);
    }
    #pragma unroll
    for (int p = 0; p < 4; p++) {
        int lin = p * 256 + tid;
        int row = lin >> 3, kg = lin & 7;
        cp16(st + 16384 + swz(row, kg), B + (size_t)(n0 + row) * kdim + kglob + kg * 8);
    }
}

__global__ void __launch_bounds__(256, 2)
gemm_mma(const __half* __restrict__ Abase, const __half* __restrict__ Bbase,
         float* __restrict__ Cf, __half* __restrict__ Ch,
         const float* __restrict__ bg, const float* __restrict__ bo,
         int kdim, int nch,
         size_t strideAz, size_t strideBz, size_t strideCz, int mode) {
    const int z = blockIdx.z;
    const int n0 = blockIdx.x * BN;
    const int m0 = blockIdx.y * BM;
    const int tid = threadIdx.x;
    const int wid = tid >> 5;
    const int lane = tid & 31;
    const int wm = wid & 1;
    const int wn = wid >> 1;

    const __half* A = Abase + (size_t)z * strideAz;
    const __half* B = Bbase + (size_t)z * strideBz;
    const float* bias = z ? bo : bg;

    const uint32_t sbase = smem_u32(dynsmem);

    float acc[4][4][4];
    #pragma unroll
    for (int i = 0; i < 4; i++)
        #pragma unroll
        for (int j = 0; j < 4; j++)
            #pragma unroll
            for (int r = 0; r < 4; r++) acc[i][j][r] = 0.0f;

    const int a_rb = wm * 64 + (lane & 15);
    const int a_gs = lane >> 4;
    const int b_rb = wn * 32 + (lane & 7) + ((lane & 16) >> 1);
    const int b_gs = (lane >> 3) & 1;

    load_chunk(sbase, 0, 0, kdim, A, B, m0, n0, tid); CP_COMMIT();
    load_chunk(sbase, 1, BK, kdim, A, B, m0, n0, tid); CP_COMMIT();

    for (int kc = 0; kc < nch; kc++) {
        CP_WAIT1();
        __syncthreads();
        if (kc + 2 < nch)
            load_chunk(sbase, (kc + 2) % NSTG, (kc + 2) * BK, kdim, A, B, m0, n0, tid);
        CP_COMMIT();

        const uint32_t sA = sbase + (kc % NSTG) * STG_BYTES;
        const uint32_t sB = sA + 16384;
        #pragma unroll
        for (int k4 = 0; k4 < 4; k4++) {
            uint32_t a[4][4];
            #pragma unroll
            for (int mi = 0; mi < 4; mi++)
                ldmx4(sA + swz(a_rb + mi * 16, k4 * 2 + a_gs),
                      a[mi][0], a[mi][1], a[mi][2], a[mi][3]);
            #pragma unroll
            for (int npp = 0; npp < 2; npp++) {
                uint32_t b0, b1, b2, b3;
                ldmx4(sB + swz(b_rb + npp * 16, k4 * 2 + b_gs), b0, b1, b2, b3);
                #pragma unroll
                for (int mi = 0; mi < 4; mi++) {
                    mma16816(acc[mi][npp*2][0], acc[mi][npp*2][1], acc[mi][npp*2][2], acc[mi][npp*2][3],
                             a[mi][0], a[mi][1], a[mi][2], a[mi][3], b0, b1);
                    mma16816(acc[mi][npp*2+1][0], acc[mi][npp*2+1][1], acc[mi][npp*2+1][2], acc[mi][npp*2+1][3],
                             a[mi][0], a[mi][1], a[mi][2], a[mi][3], b2, b3);
                }
            }
        }
    }

    // epilogue
    const int row_in = lane >> 2;
    const int col_in = (lane & 3) * 2;
    if (mode == 0) {
        float* C = Cf + (size_t)z * strideCz;
        #pragma unroll
        for (int np = 0; np < 4; np++) {
            const int col = n0 + wn * 32 + np * 8 + col_in;
            const float bx = __ldg(bias + col);
            const float by = __ldg(bias + col + 1);
            #pragma unroll
            for (int mi = 0; mi < 4; mi++) {
                const int r0 = m0 + wm * 64 + mi * 16 + row_in;
                *(float2*)(C + (size_t)r0 * DLAT + col) =
                    make_float2(acc[mi][np][0] + bx, acc[mi][np][1] + by);
                *(float2*)(C + (size_t)(r0 + 8) * DLAT + col) =
                    make_float2(acc[mi][np][2] + bx, acc[mi][np][3] + by);
            }
        }
    } else {
        __half* C = Ch + (size_t)z * strideCz;
        #pragma unroll
        for (int np = 0; np < 4; np++) {
            const int col = n0 + wn * 32 + np * 8 + col_in;
            #pragma unroll
            for (int mi = 0; mi < 4; mi++) {
                const int r0 = m0 + wm * 64 + mi * 16 + row_in;
                *(__half2*)(C + (size_t)r0 * DLAT + col) =
                    __floats2half2_rn(acc[mi][np][0], acc[mi][np][1]);
                *(__half2*)(C + (size_t)(r0 + 8) * DLAT + col) =
                    __floats2half2_rn(acc[mi][np][2], acc[mi][np][3]);
            }
        }
    }
}

// ---------------- final add: out[row] += pf2u[z][match2[row]] ----------------
__global__ void add_pf(float* __restrict__ out) {
    const int row = blockIdx.x;                 // z*(P*T) + p*T + t
    const int z = row >> 14;                    // / 16384
    const int gi = g_match2[row];
    const __half* src = g_pf2u + ((size_t)z * N_ + gi) * DLAT + threadIdx.x * 4;
    float* dst = out + (size_t)row * DLAT + threadIdx.x * 4;
    uint2 hv = *(const uint2*)src;
    float4 v = *(float4*)dst;
    float2 f0 = __half22float2(*(__half2*)&hv.x);
    float2 f1 = __half22float2(*(__half2*)&hv.y);
    v.x += f0.x; v.y += f0.y; v.z += f1.x; v.w += f1.y;
    *(float4*)dst = v;
}

// ---------------- launch ----------------
extern "C" void kernel_launch(void* const* d_in, const int* in_sizes, int n_in,
                              void* d_out, int out_size) {
    const float* object_surface = (const float*)d_in[0];
    const float* pre_pts        = (const float*)d_in[1];
    const float* pre_feats      = (const float*)d_in[2];
    const float* geo_raw        = (const float*)d_in[3];
    const float* obj_raw        = (const float*)d_in[4];
    const float* local_pc       = (const float*)d_in[5];
    const float* global_pc      = (const float*)d_in[6];
    const float* Wg             = (const float*)d_in[7];
    const float* bg             = (const float*)d_in[8];
    const float* Wo             = (const float*)d_in[9];
    const float* bo             = (const float*)d_in[10];
    float* out = (float*)d_out;

    static cudaStream_t s2 = nullptr;
    static cudaEvent_t evFork = nullptr, evW = nullptr, evS2 = nullptr;
    static bool inited = false;
    if (!inited) {
        cudaFuncSetAttribute(gemm_mma, cudaFuncAttributeMaxDynamicSharedMemorySize, GEMM_SMEM);
        cudaStreamCreateWithFlags(&s2, cudaStreamNonBlocking);
        cudaEventCreateWithFlags(&evFork, cudaEventDisableTiming);
        cudaEventCreateWithFlags(&evW, cudaEventDisableTiming);
        cudaEventCreateWithFlags(&evS2, cudaEventDisableTiming);
        inited = true;
    }

    __half* gA  = nullptr; cudaGetSymbolAddress((void**)&gA,  g_A);
    __half* gPF = nullptr; cudaGetSymbolAddress((void**)&gPF, g_PF);
    __half* gB1 = nullptr; cudaGetSymbolAddress((void**)&gB1, g_B1);
    __half* gB2 = nullptr; cudaGetSymbolAddress((void**)&gB2, g_B2);
    __half* gPU = nullptr; cudaGetSymbolAddress((void**)&gPU, g_pf2u);

    // fork s2
    cudaEventRecord(evFork, 0);
    cudaStreamWaitEvent(s2, evFork, 0);

    // s1: conversions, then MAIN GEMM immediately (no NN dependency)
    convW<<<dim3(DIN / 32, DLAT / 32, 2), dim3(32, 8)>>>(Wg, Wo);
    cudaEventRecord(evW, 0);
    convA<<<dim3(P_ * T_, 2), 256>>>(geo_raw, obj_raw);
    gemm_mma<<<dim3(DLAT / BN, (P_ * T_) / BM, 2), 256, GEMM_SMEM>>>(
        gA, gB1, out, nullptr, bg, bo,
        DLAT, DLAT / BK, (size_t)(P_ * T_) * DLAT, (size_t)DLAT * DLAT,
        (size_t)(P_ * T_) * DLAT, 0);

    // s2: nn1 -> gatherPF -> pf2u GEMM (needs convW) -> match
    nn1_partial<<<dim3(N_ / 512, MSPLIT), 128, 0, s2>>>(object_surface, pre_pts);
    nn1_reduce<<<N_ / 256, 256, 0, s2>>>();
    gatherPF<<<N_, DFEAT / 4, 0, s2>>>(pre_feats);
    cudaStreamWaitEvent(s2, evW, 0);
    gemm_mma<<<dim3(DLAT / BN, N_ / BM, 2), 256, GEMM_SMEM, s2>>>(
        gPF, gB2, nullptr, gPU, nullptr, nullptr,
        DFEAT, DFEAT / BK, 0, (size_t)DLAT * DFEAT, (size_t)N_ * DLAT, 1);
    match_partial<<<dim3(T_ / 1024, P_, 2 * NSCH), 256, 0, s2>>>(object_surface, local_pc, global_pc);
    match_reduce<<<2 * P_ * T_ / 256, 256, 0, s2>>>();
    cudaEventRecord(evS2, s2);

    // join: final gather-add
    cudaStreamWaitEvent(0, evS2, 0);
    add_pf<<<2 * P_ * T_, 256>>>(out);
}

// round 11
// speedup vs baseline: 1.1189x; 1.1189x over previous
#include <cuda_runtime.h>
#include <cuda_fp16.h>
#include <cstdint>

#define P_    8
#define T_    2048
#define N_    8192
#define M_    20000
#define DLAT  1024
#define DFEAT 512
#define DIN   1536
#define MSPLIT 20
#define MCHUNK 1000
#define NSCH  8
#define SCHSZ 1024

// ---- GEMM config (round-5/8 proven shape) ----
#define BM 128
#define BN 128
#define BK 64
#define NSTG 3
#define STG_BYTES 32768                // A 16K + B 16K
#define GEMM_SMEM (NSTG * STG_BYTES)   // 96KB

// ---------------- scratch ----------------
__device__ float g_part_d[N_ * MSPLIT];
__device__ int   g_part_i[N_ * MSPLIT];
__device__ int   g_nearest[N_];
__device__ float g_mp_d[2 * P_ * NSCH * T_];
__device__ int   g_mp_i[2 * P_ * NSCH * T_];
__device__ int   g_match2[2 * P_ * T_];          // [which][p][t] -> obj-point idx
__device__ __half g_A[2L * P_ * T_ * DLAT];      // [z][m][k<1024] fp16
__device__ __half g_PF[(size_t)N_ * DFEAT];      // fp16 feats per obj point
__device__ __half g_B1[2L * DLAT * DLAT];        // W[:1024]^T fp16 [z][n][k]
__device__ __half g_B2[2L * DLAT * DFEAT];       // W[1024:]^T fp16 [z][n][k]
__device__ float g_pf2u[2L * N_ * DLAT];         // fp32 pf @ W2 per obj point

// ---------------- helpers ----------------
__device__ __forceinline__ uint32_t smem_u32(const void* p) {
    uint32_t a;
    asm("{ .reg .u64 t; cvta.to.shared.u64 t, %1; cvt.u32.u64 %0, t; }" : "=r"(a) : "l"(p));
    return a;
}
__device__ __forceinline__ void cp16(uint32_t dst, const void* src) {
    asm volatile("cp.async.cg.shared.global [%0], [%1], 16;" :: "r"(dst), "l"(src) : "memory");
}
#define CP_COMMIT() asm volatile("cp.async.commit_group;" ::: "memory")
#define CP_WAIT1()  asm volatile("cp.async.wait_group 1;" ::: "memory")

__device__ __forceinline__ void ldmx4(uint32_t addr, uint32_t& r0, uint32_t& r1,
                                      uint32_t& r2, uint32_t& r3) {
    asm volatile("ldmatrix.sync.aligned.m8n8.x4.shared.b16 {%0,%1,%2,%3}, [%4];"
                 : "=r"(r0), "=r"(r1), "=r"(r2), "=r"(r3) : "r"(addr));
}
__device__ __forceinline__ void mma16816(float& c0, float& c1, float& c2, float& c3,
                                         uint32_t a0, uint32_t a1, uint32_t a2, uint32_t a3,
                                         uint32_t b0, uint32_t b1) {
    asm volatile("mma.sync.aligned.m16n8k16.row.col.f32.f16.f16.f32 "
                 "{%0,%1,%2,%3}, {%4,%5,%6,%7}, {%8,%9}, {%0,%1,%2,%3};"
                 : "+f"(c0), "+f"(c1), "+f"(c2), "+f"(c3)
                 : "r"(a0), "r"(a1), "r"(a2), "r"(a3), "r"(b0), "r"(b1));
}
__device__ __forceinline__ uint32_t swz(int row, int kg) {
    return (uint32_t)(row * 128 + ((kg ^ (row & 7)) << 4));
}
__device__ __forceinline__ uint2 pack4h(float4 v) {
    __half hx = __float2half_rn(v.x), hy = __float2half_rn(v.y);
    __half hz = __float2half_rn(v.z), hw = __float2half_rn(v.w);
    uint2 r;
    r.x = ((uint32_t)*(uint16_t*)&hy << 16) | (uint32_t)*(uint16_t*)&hx;
    r.y = ((uint32_t)*(uint16_t*)&hw << 16) | (uint32_t)*(uint16_t*)&hz;
    return r;
}

// ---------------- kernel 1: obj_pts[0] vs precomputed_points ----------------
// grid (N/1024, MSPLIT), block 256, 4 q/thread, 1000-candidate chunks
__global__ void nn1_partial(const float* __restrict__ os, const float* __restrict__ pts) {
    __shared__ float4 sP[MCHUNK];
    const int ms = blockIdx.y;
    const int m0 = ms * MCHUNK;
    for (int i = threadIdx.x; i < MCHUNK; i += 256) {
        float x = pts[(size_t)(m0 + i) * 3 + 0];
        float y = pts[(size_t)(m0 + i) * 3 + 1];
        float z = pts[(size_t)(m0 + i) * 3 + 2];
        sP[i] = make_float4(x, y, z, x * x + y * y + z * z);
    }
    __syncthreads();
    float qx[4], qy[4], qz[4], best[4];
    int bi[4];
    #pragma unroll
    for (int u = 0; u < 4; u++) {
        const int q = blockIdx.x * 1024 + u * 256 + threadIdx.x;
        qx[u] = -2.0f * os[(size_t)q * 6 + 0];
        qy[u] = -2.0f * os[(size_t)q * 6 + 1];
        qz[u] = -2.0f * os[(size_t)q * 6 + 2];
        best[u] = 3.4e38f;
        bi[u] = 0;
    }
    #pragma unroll 4
    for (int i = 0; i < MCHUNK; i++) {
        float4 c = sP[i];
        #pragma unroll
        for (int u = 0; u < 4; u++) {
            float d = fmaf(qx[u], c.x, fmaf(qy[u], c.y, fmaf(qz[u], c.z, c.w)));
            if (d < best[u]) { best[u] = d; bi[u] = i; }
        }
    }
    #pragma unroll
    for (int u = 0; u < 4; u++) {
        const int q = blockIdx.x * 1024 + u * 256 + threadIdx.x;
        g_part_d[q * MSPLIT + ms] = best[u];
        g_part_i[q * MSPLIT + ms] = m0 + bi[u];
    }
}

__global__ void nn1_reduce() {
    const int q = blockIdx.x * blockDim.x + threadIdx.x;
    float best = g_part_d[q * MSPLIT];
    int bi = g_part_i[q * MSPLIT];
    #pragma unroll
    for (int s = 1; s < MSPLIT; s++) {
        float d = g_part_d[q * MSPLIT + s];
        if (d < best) { best = d; bi = g_part_i[q * MSPLIT + s]; }
    }
    g_nearest[q] = bi;
}

// ---------------- kernel 2: match partial + reduce (independent of nn1) ----------------
__global__ void match_partial(const float* __restrict__ os,
                              const float* __restrict__ local_pc,
                              const float* __restrict__ global_pc) {
    __shared__ float4 sP[SCHSZ];
    const int p = blockIdx.y;
    const int which = blockIdx.z >> 3;
    const int ch = blockIdx.z & 7;
    const int nt = ch * SCHSZ;
    const float* qsrc = (which == 0) ? local_pc : global_pc;
    const int tb = blockIdx.x * 1024 + threadIdx.x;

    for (int i = threadIdx.x; i < SCHSZ; i += 256) {
        size_t bsrc = ((size_t)p * N_ + nt + i) * 6;
        float x = os[bsrc + 0], y = os[bsrc + 1], z = os[bsrc + 2];
        sP[i] = make_float4(x, y, z, x * x + y * y + z * z);
    }

    float qx[4], qy[4], qz[4], best[4];
    int bi[4];
    #pragma unroll
    for (int u = 0; u < 4; u++) {
        const size_t qb = ((size_t)p * T_ + tb + u * 256) * 3;
        qx[u] = -2.0f * qsrc[qb + 0];
        qy[u] = -2.0f * qsrc[qb + 1];
        qz[u] = -2.0f * qsrc[qb + 2];
        best[u] = 3.4e38f;
        bi[u] = 0;
    }
    __syncthreads();
    #pragma unroll 4
    for (int i = 0; i < SCHSZ; i++) {
        float4 c = sP[i];
        #pragma unroll
        for (int u = 0; u < 4; u++) {
            float d = fmaf(qx[u], c.x, fmaf(qy[u], c.y, fmaf(qz[u], c.z, c.w)));
            if (d < best[u]) { best[u] = d; bi[u] = nt + i; }
        }
    }
    #pragma unroll
    for (int u = 0; u < 4; u++) {
        size_t o = (((size_t)which * P_ + p) * NSCH + ch) * T_ + tb + u * 256;
        g_mp_d[o] = best[u];
        g_mp_i[o] = bi[u];
    }
}

__global__ void match_reduce() {
    const int g = blockIdx.x * 256 + threadIdx.x;
    const int wp = g / T_;
    const int t = g % T_;
    size_t base = ((size_t)wp * NSCH) * T_ + t;
    float best = g_mp_d[base];
    int bi = g_mp_i[base];
    #pragma unroll
    for (int c = 1; c < NSCH; c++) {
        float d = g_mp_d[base + (size_t)c * T_];
        if (d < best) { best = d; bi = g_mp_i[base + (size_t)c * T_]; }
    }
    g_match2[g] = bi;
}

// ---------------- conversions ----------------
__global__ void convA(const float* __restrict__ geo_raw, const float* __restrict__ obj_raw) {
    const int z = blockIdx.y;
    const int m = blockIdx.x;
    const float* src = (z ? obj_raw : geo_raw) + (size_t)m * DLAT + threadIdx.x * 4;
    float4 v = *(const float4*)src;
    size_t base = ((size_t)z * (P_ * T_) + m) * DLAT + threadIdx.x * 4;
    *(uint2*)(g_A + base) = pack4h(v);
}

__global__ void gatherPF(const float* __restrict__ pf) {
    const int q = blockIdx.x;
    const int fi = g_nearest[q];
    float4 v = *(const float4*)(pf + (size_t)fi * DFEAT + threadIdx.x * 4);
    *(uint2*)(g_PF + (size_t)q * DFEAT + threadIdx.x * 4) = pack4h(v);
}

__global__ void convW(const float* __restrict__ Wg, const float* __restrict__ Wo) {
    __shared__ float tile[32][33];
    const int g = blockIdx.z;
    const float* W = g ? Wo : Wg;
    const int kb = blockIdx.x * 32, nb = blockIdx.y * 32;
    for (int i = threadIdx.y; i < 32; i += 8)
        tile[i][threadIdx.x] = W[(size_t)(kb + i) * DLAT + nb + threadIdx.x];
    __syncthreads();
    const int k = kb + threadIdx.x;
    for (int i = threadIdx.y; i < 32; i += 8) {
        __half h = __float2half_rn(tile[threadIdx.x][i]);
        const int n = nb + i;
        if (k < DLAT)
            g_B1[(size_t)g * DLAT * DLAT + (size_t)n * DLAT + k] = h;
        else
            g_B2[(size_t)g * DLAT * DFEAT + (size_t)n * DFEAT + (k - DLAT)] = h;
    }
}

// ---------------- GEMM: mode 1 = fp32 C raw ; mode 2 = fp32 C + bias + pf2u gather ----------------
extern __shared__ char dynsmem[];

__device__ __forceinline__ void load_chunk(uint32_t sbase, int stage, int kglob, int kdim,
                                           const __half* A, const __half* B,
                                           int m0, int n0, int tid) {
    const uint32_t st = sbase + stage * STG_BYTES;
    #pragma unroll
    for (int p = 0; p < 4; p++) {
        int lin = p * 256 + tid;
        int row = lin >> 3, kg = lin & 7;
        cp16(st + swz(row, kg), A + (size_t)(m0 + row) * kdim + kglob + kg * 8);
    }
    #pragma unroll
    for (int p = 0; p < 4; p++) {
        int lin = p * 256 + tid;
        int row = lin >> 3, kg = lin & 7;
        cp16(st + 16384 + swz(row, kg), B + (size_t)(n0 + row) * kdim + kglob + kg * 8);
    }
}

__global__ void __launch_bounds__(256, 2)
gemm_mma(const __half* __restrict__ Abase, const __half* __restrict__ Bbase,
         float* __restrict__ Cbase,
         const float* __restrict__ bg, const float* __restrict__ bo,
         int kdim, int nch,
         size_t strideAz, size_t strideBz, size_t strideCz, int mode) {
    const int z = blockIdx.z;
    const int n0 = blockIdx.x * BN;
    const int m0 = blockIdx.y * BM;
    const int tid = threadIdx.x;
    const int wid = tid >> 5;
    const int lane = tid & 31;
    const int wm = wid & 1;
    const int wn = wid >> 1;

    const __half* A = Abase + (size_t)z * strideAz;
    const __half* B = Bbase + (size_t)z * strideBz;
    float* C = Cbase + (size_t)z * strideCz;
    const float* bias = z ? bo : bg;

    const uint32_t sbase = smem_u32(dynsmem);

    float acc[4][4][4];
    #pragma unroll
    for (int i = 0; i < 4; i++)
        #pragma unroll
        for (int j = 0; j < 4; j++)
            #pragma unroll
            for (int r = 0; r < 4; r++) acc[i][j][r] = 0.0f;

    const int a_rb = wm * 64 + (lane & 15);
    const int a_gs = lane >> 4;
    const int b_rb = wn * 32 + (lane & 7) + ((lane & 16) >> 1);
    const int b_gs = (lane >> 3) & 1;

    load_chunk(sbase, 0, 0, kdim, A, B, m0, n0, tid); CP_COMMIT();
    load_chunk(sbase, 1, BK, kdim, A, B, m0, n0, tid); CP_COMMIT();

    for (int kc = 0; kc < nch; kc++) {
        CP_WAIT1();
        __syncthreads();
        if (kc + 2 < nch)
            load_chunk(sbase, (kc + 2) % NSTG, (kc + 2) * BK, kdim, A, B, m0, n0, tid);
        CP_COMMIT();

        const uint32_t sA = sbase + (kc % NSTG) * STG_BYTES;
        const uint32_t sB = sA + 16384;
        #pragma unroll
        for (int k4 = 0; k4 < 4; k4++) {
            uint32_t a[4][4];
            #pragma unroll
            for (int mi = 0; mi < 4; mi++)
                ldmx4(sA + swz(a_rb + mi * 16, k4 * 2 + a_gs),
                      a[mi][0], a[mi][1], a[mi][2], a[mi][3]);
            #pragma unroll
            for (int npp = 0; npp < 2; npp++) {
                uint32_t b0, b1, b2, b3;
                ldmx4(sB + swz(b_rb + npp * 16, k4 * 2 + b_gs), b0, b1, b2, b3);
                #pragma unroll
                for (int mi = 0; mi < 4; mi++) {
                    mma16816(acc[mi][npp*2][0], acc[mi][npp*2][1], acc[mi][npp*2][2], acc[mi][npp*2][3],
                             a[mi][0], a[mi][1], a[mi][2], a[mi][3], b0, b1);
                    mma16816(acc[mi][npp*2+1][0], acc[mi][npp*2+1][1], acc[mi][npp*2+1][2], acc[mi][npp*2+1][3],
                             a[mi][0], a[mi][1], a[mi][2], a[mi][3], b2, b3);
                }
            }
        }
    }

    // epilogue
    const int row_in = lane >> 2;
    const int col_in = (lane & 3) * 2;

    int gi0[4], gi1[4];
    const float* pfz = g_pf2u + (size_t)z * N_ * DLAT;
    if (mode == 2) {
        const int* m2 = g_match2 + (size_t)z * (P_ * T_);
        #pragma unroll
        for (int mi = 0; mi < 4; mi++) {
            const int r0 = m0 + wm * 64 + mi * 16 + row_in;
            gi0[mi] = __ldg(m2 + r0);
            gi1[mi] = __ldg(m2 + r0 + 8);
        }
    }

    #pragma unroll
    for (int np = 0; np < 4; np++) {
        const int col = n0 + wn * 32 + np * 8 + col_in;
        float bx = 0.0f, by = 0.0f;
        if (mode != 1) { bx = __ldg(bias + col); by = __ldg(bias + col + 1); }
        #pragma unroll
        for (int mi = 0; mi < 4; mi++) {
            const int r0 = m0 + wm * 64 + mi * 16 + row_in;
            float2 c0 = make_float2(acc[mi][np][0] + bx, acc[mi][np][1] + by);
            float2 c1 = make_float2(acc[mi][np][2] + bx, acc[mi][np][3] + by);
            if (mode == 2) {
                float2 p0 = *(const float2*)(pfz + (size_t)gi0[mi] * DLAT + col);
                float2 p1 = *(const float2*)(pfz + (size_t)gi1[mi] * DLAT + col);
                c0.x += p0.x; c0.y += p0.y;
                c1.x += p1.x; c1.y += p1.y;
            }
            *(float2*)(C + (size_t)r0 * DLAT + col) = c0;
            *(float2*)(C + (size_t)(r0 + 8) * DLAT + col) = c1;
        }
    }
}

// ---------------- launch ----------------
extern "C" void kernel_launch(void* const* d_in, const int* in_sizes, int n_in,
                              void* d_out, int out_size) {
    const float* object_surface = (const float*)d_in[0];
    const float* pre_pts        = (const float*)d_in[1];
    const float* pre_feats      = (const float*)d_in[2];
    const float* geo_raw        = (const float*)d_in[3];
    const float* obj_raw        = (const float*)d_in[4];
    const float* local_pc       = (const float*)d_in[5];
    const float* global_pc      = (const float*)d_in[6];
    const float* Wg             = (const float*)d_in[7];
    const float* bg             = (const float*)d_in[8];
    const float* Wo             = (const float*)d_in[9];
    const float* bo             = (const float*)d_in[10];
    float* out = (float*)d_out;

    static cudaStream_t s2 = nullptr, s3 = nullptr;
    static cudaEvent_t evFork = nullptr, evW = nullptr, evS2 = nullptr, evS3 = nullptr;
    static bool inited = false;
    if (!inited) {
        cudaFuncSetAttribute(gemm_mma, cudaFuncAttributeMaxDynamicSharedMemorySize, GEMM_SMEM);
        cudaStreamCreateWithFlags(&s2, cudaStreamNonBlocking);
        cudaStreamCreateWithFlags(&s3, cudaStreamNonBlocking);
        cudaEventCreateWithFlags(&evFork, cudaEventDisableTiming);
        cudaEventCreateWithFlags(&evW, cudaEventDisableTiming);
        cudaEventCreateWithFlags(&evS2, cudaEventDisableTiming);
        cudaEventCreateWithFlags(&evS3, cudaEventDisableTiming);
        inited = true;
    }

    __half* gA  = nullptr; cudaGetSymbolAddress((void**)&gA,  g_A);
    __half* gPF = nullptr; cudaGetSymbolAddress((void**)&gPF, g_PF);
    __half* gB1 = nullptr; cudaGetSymbolAddress((void**)&gB1, g_B1);
    __half* gB2 = nullptr; cudaGetSymbolAddress((void**)&gB2, g_B2);
    float* gPU  = nullptr; cudaGetSymbolAddress((void**)&gPU, g_pf2u);

    // fork
    cudaEventRecord(evFork, 0);
    cudaStreamWaitEvent(s2, evFork, 0);
    cudaStreamWaitEvent(s3, evFork, 0);

    // s1: conversions
    convW<<<dim3(DIN / 32, DLAT / 32, 2), dim3(32, 8)>>>(Wg, Wo);
    cudaEventRecord(evW, 0);
    convA<<<dim3(P_ * T_, 2), 256>>>(geo_raw, obj_raw);

    // s2: nn1 -> gatherPF -> pf2u GEMM (needs convW)
    nn1_partial<<<dim3(N_ / 1024, MSPLIT), 256, 0, s2>>>(object_surface, pre_pts);
    nn1_reduce<<<N_ / 256, 256, 0, s2>>>();
    gatherPF<<<N_, DFEAT / 4, 0, s2>>>(pre_feats);
    cudaStreamWaitEvent(s2, evW, 0);
    gemm_mma<<<dim3(DLAT / BN, N_ / BM, 2), 256, GEMM_SMEM, s2>>>(
        gPF, gB2, gPU, nullptr, nullptr,
        DFEAT, DFEAT / BK, 0, (size_t)DLAT * DFEAT, (size_t)N_ * DLAT, 1);
    cudaEventRecord(evS2, s2);

    // s3: match chain (independent of nn1)
    match_partial<<<dim3(T_ / 1024, P_, 2 * NSCH), 256, 0, s3>>>(object_surface, local_pc, global_pc);
    match_reduce<<<2 * P_ * T_ / 256, 256, 0, s3>>>();
    cudaEventRecord(evS3, s3);

    // join: main GEMM with fused bias + pf2u-gather epilogue
    cudaStreamWaitEvent(0, evS2, 0);
    cudaStreamWaitEvent(0, evS3, 0);
    gemm_mma<<<dim3(DLAT / BN, (P_ * T_) / BM, 2), 256, GEMM_SMEM>>>(
        gA, gB1, out, bg, bo,
        DLAT, DLAT / BK, (size_t)(P_ * T_) * DLAT, (size_t)DLAT * DLAT,
        (size_t)(P_ * T_) * DLAT, 2);
}

// round 12
// speedup vs baseline: 1.1852x; 1.0593x over previous
#include <cuda_runtime.h>
#include <cuda_fp16.h>
#include <cstdint>

#define P_    8
#define T_    2048
#define N_    8192
#define M_    20000
#define DLAT  1024
#define DFEAT 512
#define DIN   1536
#define MSPLIT 20
#define MCHUNK 1000
#define NSCH  8
#define SCHSZ 1024

// ---- GEMM config (round-5/8 proven shape) ----
#define BM 128
#define BN 128
#define BK 64
#define NSTG 3
#define STG_BYTES 32768                // A 16K + B 16K
#define GEMM_SMEM (NSTG * STG_BYTES)   // 96KB

// ---------------- scratch ----------------
__device__ float g_part_d[N_ * MSPLIT];
__device__ int   g_part_i[N_ * MSPLIT];
__device__ int   g_nearest[N_];
__device__ float g_mp_d[2 * P_ * NSCH * T_];
__device__ int   g_mp_i[2 * P_ * NSCH * T_];
__device__ int   g_match2[2 * P_ * T_];          // [which][p][t] -> obj-point idx
__device__ __half g_A[2L * P_ * T_ * DLAT];      // [z][m][k<1024] fp16
__device__ __half g_PF[(size_t)N_ * DFEAT];      // fp16 feats per obj point
__device__ __half g_B1[2L * DLAT * DLAT];        // W[:1024]^T fp16 [z][n][k]
__device__ __half g_B2[2L * DLAT * DFEAT];       // W[1024:]^T fp16 [z][n][k]
__device__ float g_pf2u[2L * N_ * DLAT];         // fp32 pf @ W2 per obj point

// ---------------- helpers ----------------
__device__ __forceinline__ uint32_t smem_u32(const void* p) {
    uint32_t a;
    asm("{ .reg .u64 t; cvta.to.shared.u64 t, %1; cvt.u32.u64 %0, t; }" : "=r"(a) : "l"(p));
    return a;
}
__device__ __forceinline__ void cp16(uint32_t dst, const void* src) {
    asm volatile("cp.async.cg.shared.global [%0], [%1], 16;" :: "r"(dst), "l"(src) : "memory");
}
#define CP_COMMIT() asm volatile("cp.async.commit_group;" ::: "memory")
#define CP_WAIT1()  asm volatile("cp.async.wait_group 1;" ::: "memory")

__device__ __forceinline__ void ldmx4(uint32_t addr, uint32_t& r0, uint32_t& r1,
                                      uint32_t& r2, uint32_t& r3) {
    asm volatile("ldmatrix.sync.aligned.m8n8.x4.shared.b16 {%0,%1,%2,%3}, [%4];"
                 : "=r"(r0), "=r"(r1), "=r"(r2), "=r"(r3) : "r"(addr));
}
__device__ __forceinline__ void mma16816(float& c0, float& c1, float& c2, float& c3,
                                         uint32_t a0, uint32_t a1, uint32_t a2, uint32_t a3,
                                         uint32_t b0, uint32_t b1) {
    asm volatile("mma.sync.aligned.m16n8k16.row.col.f32.f16.f16.f32 "
                 "{%0,%1,%2,%3}, {%4,%5,%6,%7}, {%8,%9}, {%0,%1,%2,%3};"
                 : "+f"(c0), "+f"(c1), "+f"(c2), "+f"(c3)
                 : "r"(a0), "r"(a1), "r"(a2), "r"(a3), "r"(b0), "r"(b1));
}
__device__ __forceinline__ uint32_t swz(int row, int kg) {
    return (uint32_t)(row * 128 + ((kg ^ (row & 7)) << 4));
}
__device__ __forceinline__ uint2 pack4h(float4 v) {
    __half hx = __float2half_rn(v.x), hy = __float2half_rn(v.y);
    __half hz = __float2half_rn(v.z), hw = __float2half_rn(v.w);
    uint2 r;
    r.x = ((uint32_t)*(uint16_t*)&hy << 16) | (uint32_t)*(uint16_t*)&hx;
    r.y = ((uint32_t)*(uint16_t*)&hw << 16) | (uint32_t)*(uint16_t*)&hz;
    return r;
}

// ---------------- kernel 1: obj_pts[0] vs precomputed_points ----------------
// grid (N/1024, MSPLIT), block 256, 4 q/thread, 1000-candidate chunks
__global__ void nn1_partial(const float* __restrict__ os, const float* __restrict__ pts) {
    __shared__ float4 sP[MCHUNK];
    const int ms = blockIdx.y;
    const int m0 = ms * MCHUNK;
    for (int i = threadIdx.x; i < MCHUNK; i += 256) {
        float x = pts[(size_t)(m0 + i) * 3 + 0];
        float y = pts[(size_t)(m0 + i) * 3 + 1];
        float z = pts[(size_t)(m0 + i) * 3 + 2];
        sP[i] = make_float4(x, y, z, x * x + y * y + z * z);
    }
    __syncthreads();
    float qx[4], qy[4], qz[4], best[4];
    int bi[4];
    #pragma unroll
    for (int u = 0; u < 4; u++) {
        const int q = blockIdx.x * 1024 + u * 256 + threadIdx.x;
        qx[u] = -2.0f * os[(size_t)q * 6 + 0];
        qy[u] = -2.0f * os[(size_t)q * 6 + 1];
        qz[u] = -2.0f * os[(size_t)q * 6 + 2];
        best[u] = 3.4e38f;
        bi[u] = 0;
    }
    #pragma unroll 4
    for (int i = 0; i < MCHUNK; i++) {
        float4 c = sP[i];
        #pragma unroll
        for (int u = 0; u < 4; u++) {
            float d = fmaf(qx[u], c.x, fmaf(qy[u], c.y, fmaf(qz[u], c.z, c.w)));
            if (d < best[u]) { best[u] = d; bi[u] = i; }
        }
    }
    #pragma unroll
    for (int u = 0; u < 4; u++) {
        const int q = blockIdx.x * 1024 + u * 256 + threadIdx.x;
        g_part_d[q * MSPLIT + ms] = best[u];
        g_part_i[q * MSPLIT + ms] = m0 + bi[u];
    }
}

__global__ void nn1_reduce() {
    const int q = blockIdx.x * blockDim.x + threadIdx.x;
    float best = g_part_d[q * MSPLIT];
    int bi = g_part_i[q * MSPLIT];
    #pragma unroll
    for (int s = 1; s < MSPLIT; s++) {
        float d = g_part_d[q * MSPLIT + s];
        if (d < best) { best = d; bi = g_part_i[q * MSPLIT + s]; }
    }
    g_nearest[q] = bi;
}

// ---------------- kernel 2: match partial + reduce ----------------
__global__ void match_partial(const float* __restrict__ os,
                              const float* __restrict__ local_pc,
                              const float* __restrict__ global_pc) {
    __shared__ float4 sP[SCHSZ];
    const int p = blockIdx.y;
    const int which = blockIdx.z >> 3;
    const int ch = blockIdx.z & 7;
    const int nt = ch * SCHSZ;
    const float* qsrc = (which == 0) ? local_pc : global_pc;
    const int tb = blockIdx.x * 1024 + threadIdx.x;

    for (int i = threadIdx.x; i < SCHSZ; i += 256) {
        size_t bsrc = ((size_t)p * N_ + nt + i) * 6;
        float x = os[bsrc + 0], y = os[bsrc + 1], z = os[bsrc + 2];
        sP[i] = make_float4(x, y, z, x * x + y * y + z * z);
    }

    float qx[4], qy[4], qz[4], best[4];
    int bi[4];
    #pragma unroll
    for (int u = 0; u < 4; u++) {
        const size_t qb = ((size_t)p * T_ + tb + u * 256) * 3;
        qx[u] = -2.0f * qsrc[qb + 0];
        qy[u] = -2.0f * qsrc[qb + 1];
        qz[u] = -2.0f * qsrc[qb + 2];
        best[u] = 3.4e38f;
        bi[u] = 0;
    }
    __syncthreads();
    #pragma unroll 4
    for (int i = 0; i < SCHSZ; i++) {
        float4 c = sP[i];
        #pragma unroll
        for (int u = 0; u < 4; u++) {
            float d = fmaf(qx[u], c.x, fmaf(qy[u], c.y, fmaf(qz[u], c.z, c.w)));
            if (d < best[u]) { best[u] = d; bi[u] = nt + i; }
        }
    }
    #pragma unroll
    for (int u = 0; u < 4; u++) {
        size_t o = (((size_t)which * P_ + p) * NSCH + ch) * T_ + tb + u * 256;
        g_mp_d[o] = best[u];
        g_mp_i[o] = bi[u];
    }
}

__global__ void match_reduce() {
    const int g = blockIdx.x * 256 + threadIdx.x;
    const int wp = g / T_;
    const int t = g % T_;
    size_t base = ((size_t)wp * NSCH) * T_ + t;
    float best = g_mp_d[base];
    int bi = g_mp_i[base];
    #pragma unroll
    for (int c = 1; c < NSCH; c++) {
        float d = g_mp_d[base + (size_t)c * T_];
        if (d < best) { best = d; bi = g_mp_i[base + (size_t)c * T_]; }
    }
    g_match2[g] = bi;
}

// ---------------- conversions ----------------
__global__ void convA(const float* __restrict__ geo_raw, const float* __restrict__ obj_raw) {
    const int z = blockIdx.y;
    const int m = blockIdx.x;
    const float* src = (z ? obj_raw : geo_raw) + (size_t)m * DLAT + threadIdx.x * 4;
    float4 v = *(const float4*)src;
    size_t base = ((size_t)z * (P_ * T_) + m) * DLAT + threadIdx.x * 4;
    *(uint2*)(g_A + base) = pack4h(v);
}

__global__ void gatherPF(const float* __restrict__ pf) {
    const int q = blockIdx.x;
    const int fi = g_nearest[q];
    float4 v = *(const float4*)(pf + (size_t)fi * DFEAT + threadIdx.x * 4);
    *(uint2*)(g_PF + (size_t)q * DFEAT + threadIdx.x * 4) = pack4h(v);
}

__global__ void convW(const float* __restrict__ Wg, const float* __restrict__ Wo) {
    __shared__ float tile[32][33];
    const int g = blockIdx.z;
    const float* W = g ? Wo : Wg;
    const int kb = blockIdx.x * 32, nb = blockIdx.y * 32;
    for (int i = threadIdx.y; i < 32; i += 8)
        tile[i][threadIdx.x] = W[(size_t)(kb + i) * DLAT + nb + threadIdx.x];
    __syncthreads();
    const int k = kb + threadIdx.x;
    for (int i = threadIdx.y; i < 32; i += 8) {
        __half h = __float2half_rn(tile[threadIdx.x][i]);
        const int n = nb + i;
        if (k < DLAT)
            g_B1[(size_t)g * DLAT * DLAT + (size_t)n * DLAT + k] = h;
        else
            g_B2[(size_t)g * DLAT * DFEAT + (size_t)n * DFEAT + (k - DLAT)] = h;
    }
}

// ---------------- GEMM: mode 1 = fp32 C raw ; mode 2 = fp32 C + bias + pf2u gather ----------------
extern __shared__ char dynsmem[];

__device__ __forceinline__ void load_chunk(uint32_t sbase, int stage, int kglob, int kdim,
                                           const __half* A, const __half* B,
                                           int m0, int n0, int tid) {
    const uint32_t st = sbase + stage * STG_BYTES;
    #pragma unroll
    for (int p = 0; p < 4; p++) {
        int lin = p * 256 + tid;
        int row = lin >> 3, kg = lin & 7;
        cp16(st + swz(row, kg), A + (size_t)(m0 + row) * kdim + kglob + kg * 8);
    }
    #pragma unroll
    for (int p = 0; p < 4; p++) {
        int lin = p * 256 + tid;
        int row = lin >> 3, kg = lin & 7;
        cp16(st + 16384 + swz(row, kg), B + (size_t)(n0 + row) * kdim + kglob + kg * 8);
    }
}

__global__ void __launch_bounds__(256, 2)
gemm_mma(const __half* __restrict__ Abase, const __half* __restrict__ Bbase,
         float* __restrict__ Cbase,
         const float* __restrict__ bg, const float* __restrict__ bo,
         int kdim, int nch,
         size_t strideAz, size_t strideBz, size_t strideCz, int mode) {
    const int z = blockIdx.z;
    const int n0 = blockIdx.x * BN;
    const int m0 = blockIdx.y * BM;
    const int tid = threadIdx.x;
    const int wid = tid >> 5;
    const int lane = tid & 31;
    const int wm = wid & 1;
    const int wn = wid >> 1;

    const __half* A = Abase + (size_t)z * strideAz;
    const __half* B = Bbase + (size_t)z * strideBz;
    float* C = Cbase + (size_t)z * strideCz;
    const float* bias = z ? bo : bg;

    const uint32_t sbase = smem_u32(dynsmem);

    float acc[4][4][4];
    #pragma unroll
    for (int i = 0; i < 4; i++)
        #pragma unroll
        for (int j = 0; j < 4; j++)
            #pragma unroll
            for (int r = 0; r < 4; r++) acc[i][j][r] = 0.0f;

    const int a_rb = wm * 64 + (lane & 15);
    const int a_gs = lane >> 4;
    const int b_rb = wn * 32 + (lane & 7) + ((lane & 16) >> 1);
    const int b_gs = (lane >> 3) & 1;

    load_chunk(sbase, 0, 0, kdim, A, B, m0, n0, tid); CP_COMMIT();
    load_chunk(sbase, 1, BK, kdim, A, B, m0, n0, tid); CP_COMMIT();

    for (int kc = 0; kc < nch; kc++) {
        CP_WAIT1();
        __syncthreads();
        if (kc + 2 < nch)
            load_chunk(sbase, (kc + 2) % NSTG, (kc + 2) * BK, kdim, A, B, m0, n0, tid);
        CP_COMMIT();

        const uint32_t sA = sbase + (kc % NSTG) * STG_BYTES;
        const uint32_t sB = sA + 16384;
        #pragma unroll
        for (int k4 = 0; k4 < 4; k4++) {
            uint32_t a[4][4];
            #pragma unroll
            for (int mi = 0; mi < 4; mi++)
                ldmx4(sA + swz(a_rb + mi * 16, k4 * 2 + a_gs),
                      a[mi][0], a[mi][1], a[mi][2], a[mi][3]);
            #pragma unroll
            for (int npp = 0; npp < 2; npp++) {
                uint32_t b0, b1, b2, b3;
                ldmx4(sB + swz(b_rb + npp * 16, k4 * 2 + b_gs), b0, b1, b2, b3);
                #pragma unroll
                for (int mi = 0; mi < 4; mi++) {
                    mma16816(acc[mi][npp*2][0], acc[mi][npp*2][1], acc[mi][npp*2][2], acc[mi][npp*2][3],
                             a[mi][0], a[mi][1], a[mi][2], a[mi][3], b0, b1);
                    mma16816(acc[mi][npp*2+1][0], acc[mi][npp*2+1][1], acc[mi][npp*2+1][2], acc[mi][npp*2+1][3],
                             a[mi][0], a[mi][1], a[mi][2], a[mi][3], b2, b3);
                }
            }
        }
    }

    // epilogue
    const int row_in = lane >> 2;
    const int col_in = (lane & 3) * 2;

    int gi0[4], gi1[4];
    const float* pfz = g_pf2u + (size_t)z * N_ * DLAT;
    if (mode == 2) {
        const int* m2 = g_match2 + (size_t)z * (P_ * T_);
        #pragma unroll
        for (int mi = 0; mi < 4; mi++) {
            const int r0 = m0 + wm * 64 + mi * 16 + row_in;
            gi0[mi] = __ldg(m2 + r0);
            gi1[mi] = __ldg(m2 + r0 + 8);
        }
    }

    #pragma unroll
    for (int np = 0; np < 4; np++) {
        const int col = n0 + wn * 32 + np * 8 + col_in;
        float bx = 0.0f, by = 0.0f;
        if (mode != 1) { bx = __ldg(bias + col); by = __ldg(bias + col + 1); }
        #pragma unroll
        for (int mi = 0; mi < 4; mi++) {
            const int r0 = m0 + wm * 64 + mi * 16 + row_in;
            float2 c0 = make_float2(acc[mi][np][0] + bx, acc[mi][np][1] + by);
            float2 c1 = make_float2(acc[mi][np][2] + bx, acc[mi][np][3] + by);
            if (mode == 2) {
                float2 p0 = *(const float2*)(pfz + (size_t)gi0[mi] * DLAT + col);
                float2 p1 = *(const float2*)(pfz + (size_t)gi1[mi] * DLAT + col);
                c0.x += p0.x; c0.y += p0.y;
                c1.x += p1.x; c1.y += p1.y;
            }
            *(float2*)(C + (size_t)r0 * DLAT + col) = c0;
            *(float2*)(C + (size_t)(r0 + 8) * DLAT + col) = c1;
        }
    }
}

// ---------------- launch (round-8 schedule) ----------------
extern "C" void kernel_launch(void* const* d_in, const int* in_sizes, int n_in,
                              void* d_out, int out_size) {
    const float* object_surface = (const float*)d_in[0];
    const float* pre_pts        = (const float*)d_in[1];
    const float* pre_feats      = (const float*)d_in[2];
    const float* geo_raw        = (const float*)d_in[3];
    const float* obj_raw        = (const float*)d_in[4];
    const float* local_pc       = (const float*)d_in[5];
    const float* global_pc      = (const float*)d_in[6];
    const float* Wg             = (const float*)d_in[7];
    const float* bg             = (const float*)d_in[8];
    const float* Wo             = (const float*)d_in[9];
    const float* bo             = (const float*)d_in[10];
    float* out = (float*)d_out;

    static cudaStream_t s2 = nullptr;
    static cudaEvent_t evFork = nullptr, evNN = nullptr, evMatch = nullptr;
    static bool inited = false;
    if (!inited) {
        cudaFuncSetAttribute(gemm_mma, cudaFuncAttributeMaxDynamicSharedMemorySize, GEMM_SMEM);
        cudaStreamCreateWithFlags(&s2, cudaStreamNonBlocking);
        cudaEventCreateWithFlags(&evFork, cudaEventDisableTiming);
        cudaEventCreateWithFlags(&evNN, cudaEventDisableTiming);
        cudaEventCreateWithFlags(&evMatch, cudaEventDisableTiming);
        inited = true;
    }

    __half* gA  = nullptr; cudaGetSymbolAddress((void**)&gA,  g_A);
    __half* gPF = nullptr; cudaGetSymbolAddress((void**)&gPF, g_PF);
    __half* gB1 = nullptr; cudaGetSymbolAddress((void**)&gB1, g_B1);
    __half* gB2 = nullptr; cudaGetSymbolAddress((void**)&gB2, g_B2);
    float* gPU  = nullptr; cudaGetSymbolAddress((void**)&gPU, g_pf2u);

    // fork: NN chain on s2
    cudaEventRecord(evFork, 0);
    cudaStreamWaitEvent(s2, evFork, 0);

    nn1_partial<<<dim3(N_ / 1024, MSPLIT), 256, 0, s2>>>(object_surface, pre_pts);
    nn1_reduce<<<N_ / 256, 256, 0, s2>>>();
    cudaEventRecord(evNN, s2);
    match_partial<<<dim3(T_ / 1024, P_, 2 * NSCH), 256, 0, s2>>>(object_surface, local_pc, global_pc);
    match_reduce<<<2 * P_ * T_ / 256, 256, 0, s2>>>();
    cudaEventRecord(evMatch, s2);

    // main stream: conversions, then pf2u GEMM (after nn1), then big GEMM (after match)
    convW<<<dim3(DIN / 32, DLAT / 32, 2), dim3(32, 8)>>>(Wg, Wo);
    convA<<<dim3(P_ * T_, 2), 256>>>(geo_raw, obj_raw);

    cudaStreamWaitEvent(0, evNN, 0);
    gatherPF<<<N_, DFEAT / 4>>>(pre_feats);
    // pf2u[z] = g_PF @ g_B2[z]  (M=8192, N=1024, K=512), raw fp32 write
    gemm_mma<<<dim3(DLAT / BN, N_ / BM, 2), 256, GEMM_SMEM>>>(
        gPF, gB2, gPU, nullptr, nullptr,
        DFEAT, DFEAT / BK, 0, (size_t)DLAT * DFEAT, (size_t)N_ * DLAT, 1);

    cudaStreamWaitEvent(0, evMatch, 0);
    // C[z] = A[z] @ B1[z] + bias[z] + pf2u[z][match2]  (M=16384, N=1024, K=1024)
    gemm_mma<<<dim3(DLAT / BN, (P_ * T_) / BM, 2), 256, GEMM_SMEM>>>(
        gA, gB1, out, bg, bo,
        DLAT, DLAT / BK, (size_t)(P_ * T_) * DLAT, (size_t)DLAT * DLAT,
        (size_t)(P_ * T_) * DLAT, 2);
}